// round 8
// baseline (speedup 1.0000x reference)
#include <cuda_runtime.h>
#include <cstdint>

#define D0 64
#define D1 128
#define NMAX 100000
#define EMAX 1600000
#define RPB 8

// Scratch (device globals; allocation in kernel_launch is forbidden)
__device__ __align__(16) float g_t[NMAX * D0];       // 25.6 MB
__device__ __align__(16) float g_p[NMAX * D0];       // 25.6 MB
__device__ __align__(16) int   g_col[EMAX];          // 6.4 MB
__device__ int g_rowptr[NMAX + 1];
__device__ int g_cur[NMAX];
__device__ int g_cnt[NMAX];   // zero at load; re-zeroed by agg2 tail each run

// packed f32x2 FMA helpers
__device__ __forceinline__ void fma2(uint64_t& d, uint64_t a, uint64_t b) {
    asm("fma.rn.f32x2 %0, %1, %2, %0;" : "+l"(d) : "l"(a), "l"(b));
}
__device__ __forceinline__ uint64_t pack2(float v) {
    uint32_t u = __float_as_uint(v);
    uint64_t r;
    asm("mov.b64 %0, {%1, %1};" : "=l"(r) : "r"(u));
    return r;
}

// per-block int64-vs-int32 detect (odd 32-bit words all zero over 8192 = i64)
__device__ __forceinline__ bool detect64(const int* raw) {
    int nz = 0;
    for (int i = 2 * threadIdx.x + 1; i < 8192; i += 2 * blockDim.x)
        nz |= raw[i];
    return __syncthreads_or(nz) == 0;
}
__device__ __forceinline__ int eidx(const void* ei, bool is64, int i) {
    return is64 ? (int)((const long long*)ei)[i] : ((const int*)ei)[i];
}

// ---------------------------------------------------------------------------
// hist: row histogram straight off the raw edge list
// ---------------------------------------------------------------------------
__global__ __launch_bounds__(1024) void hist_k(const void* __restrict__ ei, int E) {
    bool is64 = detect64((const int*)ei);
    int stride = gridDim.x * blockDim.x;
    for (int i = blockIdx.x * blockDim.x + threadIdx.x; i < E; i += stride)
        atomicAdd(&g_cnt[eidx(ei, is64, i)], 1);
}

// ---------------------------------------------------------------------------
// scan: one-kernel exclusive prefix scan of g_cnt -> g_rowptr, g_cur
// ---------------------------------------------------------------------------
__global__ __launch_bounds__(1024) void scan_k(int Nn, int E) {
    __shared__ int sh[1024];
    __shared__ int s_off;
    int b = blockIdx.x;

    int pre = 0;
    for (int i = threadIdx.x; i < b * 1024; i += 1024) pre += g_cnt[i];
    sh[threadIdx.x] = pre;
    __syncthreads();
    #pragma unroll
    for (int off = 512; off > 0; off >>= 1) {
        if (threadIdx.x < off) sh[threadIdx.x] += sh[threadIdx.x + off];
        __syncthreads();
    }
    if (threadIdx.x == 0) s_off = sh[0];
    __syncthreads();
    int base = s_off;
    __syncthreads();

    int g = b * 1024 + threadIdx.x;
    int v = (g < Nn) ? g_cnt[g] : 0;
    sh[threadIdx.x] = v;
    __syncthreads();
    #pragma unroll
    for (int off = 1; off < 1024; off <<= 1) {
        int t = (threadIdx.x >= off) ? sh[threadIdx.x - off] : 0;
        __syncthreads();
        sh[threadIdx.x] += t;
        __syncthreads();
    }
    if (g < Nn) {
        int r = base + sh[threadIdx.x] - v;
        g_rowptr[g] = r;
        g_cur[g] = r;
    }
    if (b == 0 && threadIdx.x == 0) g_rowptr[Nn] = E;
}

// ---------------------------------------------------------------------------
// fill: CSR col array straight off the raw edge list
// ---------------------------------------------------------------------------
__global__ __launch_bounds__(1024) void fill_k(const void* __restrict__ ei, int E) {
    bool is64 = detect64((const int*)ei);
    int stride = gridDim.x * blockDim.x;
    for (int e = blockIdx.x * blockDim.x + threadIdx.x; e < E; e += stride) {
        int r = eidx(ei, is64, e);
        int c = eidx(ei, is64, e + E);
        int pos = atomicAdd(&g_cur[r], 1);
        g_col[pos] = c;
    }
}

// ---------------------------------------------------------------------------
// agg1: t[r] = (sum_{c in adj(r)} x[c]) / max(deg,1) + x[r]
// Warp per row. Indices loaded 32-at-a-time coalesced, distributed by shfl
// (26cyc) instead of per-batch dependent L2 loads (~234cyc). Half-warp per
// neighbor, float4 per lane.
// ---------------------------------------------------------------------------
__global__ __launch_bounds__(512) void agg1_k(const float4* __restrict__ x4, int Nn) {
    int w = (blockIdx.x * blockDim.x + threadIdx.x) >> 5;
    if (w >= Nn) return;
    int lane = threadIdx.x & 31;
    int cl4 = lane & 15;
    int hi  = lane >> 4;
    int s = g_rowptr[w], e = g_rowptr[w + 1];
    float4 acc = make_float4(0.f, 0.f, 0.f, 0.f);

    for (int jb = s; jb < e; jb += 32) {
        int j = jb + lane;
        int myc = (j < e) ? g_col[j] : 0;
        int cnt = e - jb; if (cnt > 32) cnt = 32;
        int q = 0;
        #pragma unroll 1
        for (; q + 8 <= cnt; q += 8) {
            int c0 = __shfl_sync(0xffffffffu, myc, q +     hi);
            int c1 = __shfl_sync(0xffffffffu, myc, q + 2 + hi);
            int c2 = __shfl_sync(0xffffffffu, myc, q + 4 + hi);
            int c3 = __shfl_sync(0xffffffffu, myc, q + 6 + hi);
            float4 v0 = __ldg(&x4[c0 * 16 + cl4]);
            float4 v1 = __ldg(&x4[c1 * 16 + cl4]);
            float4 v2 = __ldg(&x4[c2 * 16 + cl4]);
            float4 v3 = __ldg(&x4[c3 * 16 + cl4]);
            acc.x += (v0.x + v1.x) + (v2.x + v3.x);
            acc.y += (v0.y + v1.y) + (v2.y + v3.y);
            acc.z += (v0.z + v1.z) + (v2.z + v3.z);
            acc.w += (v0.w + v1.w) + (v2.w + v3.w);
        }
        #pragma unroll 1
        for (; q + 2 <= cnt; q += 2) {
            int c = __shfl_sync(0xffffffffu, myc, q + hi);
            float4 v = __ldg(&x4[c * 16 + cl4]);
            acc.x += v.x; acc.y += v.y; acc.z += v.z; acc.w += v.w;
        }
        if (q < cnt) {
            int c = __shfl_sync(0xffffffffu, myc, q);
            if (hi == 0) {
                float4 v = __ldg(&x4[c * 16 + cl4]);
                acc.x += v.x; acc.y += v.y; acc.z += v.z; acc.w += v.w;
            }
        }
    }
    acc.x += __shfl_xor_sync(0xffffffffu, acc.x, 16);
    acc.y += __shfl_xor_sync(0xffffffffu, acc.y, 16);
    acc.z += __shfl_xor_sync(0xffffffffu, acc.z, 16);
    acc.w += __shfl_xor_sync(0xffffffffu, acc.w, 16);
    if (hi == 0) {
        float inv = 1.0f / fmaxf((float)(e - s), 1.0f);
        float4 xx = __ldg(&x4[w * 16 + cl4]);
        float4 o;
        o.x = acc.x * inv + xx.x;
        o.y = acc.y * inv + xx.y;
        o.z = acc.z * inv + xx.z;
        o.w = acc.w * inv + xx.w;
        ((float4*)g_t)[w * 16 + cl4] = o;
    }
}

// ---------------------------------------------------------------------------
// mm12: fused  h = relu(t @ W1 + b1);  p = h @ W2
// Dup-packed activation staging: pack2 once per value at stage time; inner
// loops are pure LDS + FMA2.
// smem: sW1 32KB | sW2 32KB | sb1 512B | st 4*8*128*8B = 32KB -> 98816 B
// ---------------------------------------------------------------------------
__global__ __launch_bounds__(128) void mm12_k(const float* __restrict__ W1,
                                              const float* __restrict__ b1,
                                              const float* __restrict__ W2,
                                              int Nn) {
    extern __shared__ char smem_[];
    float*    sW1 = (float*)smem_;                 // [k][j] 64x128
    float*    sW2 = (float*)(smem_ + 32768);       // [k][j] 128x64
    float*    sb1 = (float*)(smem_ + 65536);
    uint64_t* st  = (uint64_t*)(smem_ + 66048);    // [warp][rr][128] packed

    int tid = threadIdx.x;
    for (int i = tid; i < D0 * D1; i += 128) sW1[i] = W1[i];
    for (int i = tid; i < D1 * D0; i += 128) sW2[i] = W2[i];
    if (tid < D1) sb1[tid] = b1[tid];
    __syncthreads();

    int warp = tid >> 5, lane = tid & 31;
    uint64_t* stw = st + warp * RPB * D1;
    float4 b4 = ((const float4*)sb1)[lane];
    int nwarps = gridDim.x * 4;
    int gw = blockIdx.x * 4 + warp;

    for (int base = gw * RPB; base < Nn; base += nwarps * RPB) {
        // stage t dup-packed: lane covers k = 2lane, 2lane+1
        #pragma unroll
        for (int rr = 0; rr < RPB; rr++) {
            int r = base + rr;
            if (r < Nn) {
                float2 tv = ((const float2*)g_t)[r * 32 + lane];
                ulonglong2 d;
                d.x = pack2(tv.x);
                d.y = pack2(tv.y);
                ((ulonglong2*)(stw + rr * D1))[lane] = d;
            }
        }
        __syncwarp();

        // GEMM1: lane owns h cols 4lane..4lane+3
        uint64_t accA[RPB], accB[RPB];
        #pragma unroll
        for (int rr = 0; rr < RPB; rr++) { accA[rr] = 0ull; accB[rr] = 0ull; }

        #pragma unroll 4
        for (int k2 = 0; k2 < D0; k2 += 2) {
            ulonglong2 a[RPB];
            #pragma unroll
            for (int rr = 0; rr < RPB; rr++)
                a[rr] = *(const ulonglong2*)(stw + rr * D1 + k2);   // broadcast
            ulonglong2 w0 = ((const ulonglong2*)(sW1 + k2 * D1))[lane];
            ulonglong2 w1 = ((const ulonglong2*)(sW1 + (k2 + 1) * D1))[lane];
            #pragma unroll
            for (int rr = 0; rr < RPB; rr++) {
                fma2(accA[rr], a[rr].x, w0.x);
                fma2(accB[rr], a[rr].x, w0.y);
                fma2(accA[rr], a[rr].y, w1.x);
                fma2(accB[rr], a[rr].y, w1.y);
            }
        }
        __syncwarp();

        // h = relu(acc+b) -> restage dup-packed at k = 4lane..4lane+3
        #pragma unroll
        for (int rr = 0; rr < RPB; rr++) {
            float2 aa = *(float2*)&accA[rr];
            float2 bb = *(float2*)&accB[rr];
            ulonglong2 d0, d1;
            d0.x = pack2(fmaxf(aa.x + b4.x, 0.f));
            d0.y = pack2(fmaxf(aa.y + b4.y, 0.f));
            d1.x = pack2(fmaxf(bb.x + b4.z, 0.f));
            d1.y = pack2(fmaxf(bb.y + b4.w, 0.f));
            ulonglong2* row = (ulonglong2*)(stw + rr * D1);
            row[2 * lane]     = d0;
            row[2 * lane + 1] = d1;
        }
        __syncwarp();

        // GEMM2: lane owns p cols 2lane..2lane+1
        uint64_t acc[RPB];
        #pragma unroll
        for (int rr = 0; rr < RPB; rr++) acc[rr] = 0ull;

        #pragma unroll 4
        for (int k2 = 0; k2 < D1; k2 += 2) {
            ulonglong2 a[RPB];
            #pragma unroll
            for (int rr = 0; rr < RPB; rr++)
                a[rr] = *(const ulonglong2*)(stw + rr * D1 + k2);
            uint64_t w0 = ((const uint64_t*)(sW2 + k2 * D0))[lane];
            uint64_t w1 = ((const uint64_t*)(sW2 + (k2 + 1) * D0))[lane];
            #pragma unroll
            for (int rr = 0; rr < RPB; rr++) {
                fma2(acc[rr], a[rr].x, w0);
                fma2(acc[rr], a[rr].y, w1);
            }
        }

        #pragma unroll
        for (int rr = 0; rr < RPB; rr++) {
            int r = base + rr;
            if (r < Nn) ((float2*)g_p)[r * 32 + lane] = *(float2*)&acc[rr];
        }
        __syncwarp();
    }
}

// ---------------------------------------------------------------------------
// agg2: out[r] = (sum_{c in adj(r)} p[c]) / max(deg,1) + p[r] + b2
// Same shfl-index gather. Tail: re-zero g_cnt for next graph replay.
// ---------------------------------------------------------------------------
__global__ __launch_bounds__(512) void agg2_k(const float* __restrict__ b2,
                                              float* __restrict__ out, int Nn) {
    int w = (blockIdx.x * blockDim.x + threadIdx.x) >> 5;
    if (w >= Nn) return;
    int lane = threadIdx.x & 31;
    int cl4 = lane & 15;
    int hi  = lane >> 4;
    const float4* p4 = (const float4*)g_p;
    int s = g_rowptr[w], e = g_rowptr[w + 1];
    float4 acc = make_float4(0.f, 0.f, 0.f, 0.f);

    for (int jb = s; jb < e; jb += 32) {
        int j = jb + lane;
        int myc = (j < e) ? g_col[j] : 0;
        int cnt = e - jb; if (cnt > 32) cnt = 32;
        int q = 0;
        #pragma unroll 1
        for (; q + 8 <= cnt; q += 8) {
            int c0 = __shfl_sync(0xffffffffu, myc, q +     hi);
            int c1 = __shfl_sync(0xffffffffu, myc, q + 2 + hi);
            int c2 = __shfl_sync(0xffffffffu, myc, q + 4 + hi);
            int c3 = __shfl_sync(0xffffffffu, myc, q + 6 + hi);
            float4 v0 = p4[c0 * 16 + cl4];
            float4 v1 = p4[c1 * 16 + cl4];
            float4 v2 = p4[c2 * 16 + cl4];
            float4 v3 = p4[c3 * 16 + cl4];
            acc.x += (v0.x + v1.x) + (v2.x + v3.x);
            acc.y += (v0.y + v1.y) + (v2.y + v3.y);
            acc.z += (v0.z + v1.z) + (v2.z + v3.z);
            acc.w += (v0.w + v1.w) + (v2.w + v3.w);
        }
        #pragma unroll 1
        for (; q + 2 <= cnt; q += 2) {
            int c = __shfl_sync(0xffffffffu, myc, q + hi);
            float4 v = p4[c * 16 + cl4];
            acc.x += v.x; acc.y += v.y; acc.z += v.z; acc.w += v.w;
        }
        if (q < cnt) {
            int c = __shfl_sync(0xffffffffu, myc, q);
            if (hi == 0) {
                float4 v = p4[c * 16 + cl4];
                acc.x += v.x; acc.y += v.y; acc.z += v.z; acc.w += v.w;
            }
        }
    }
    acc.x += __shfl_xor_sync(0xffffffffu, acc.x, 16);
    acc.y += __shfl_xor_sync(0xffffffffu, acc.y, 16);
    acc.z += __shfl_xor_sync(0xffffffffu, acc.z, 16);
    acc.w += __shfl_xor_sync(0xffffffffu, acc.w, 16);
    if (hi == 0) {
        float inv = 1.0f / fmaxf((float)(e - s), 1.0f);
        float4 pp = p4[w * 16 + cl4];
        float4 bb = __ldg(&((const float4*)b2)[cl4]);
        float4 o;
        o.x = acc.x * inv + pp.x + bb.x;
        o.y = acc.y * inv + pp.y + bb.y;
        o.z = acc.z * inv + pp.z + bb.z;
        o.w = acc.w * inv + pp.w + bb.w;
        ((float4*)out)[w * 16 + cl4] = o;
    }
    if (lane == 0) g_cnt[w] = 0;
}

// ---------------------------------------------------------------------------
extern "C" void kernel_launch(void* const* d_in, const int* in_sizes, int n_in,
                              void* d_out, int out_size) {
    const float* x   = (const float*)d_in[0];
    const void*  ei  = d_in[1];
    const float* W1  = (const float*)d_in[2];
    const float* b1  = (const float*)d_in[3];
    const float* W2  = (const float*)d_in[4];
    const float* b2  = (const float*)d_in[5];
    float*       out = (float*)d_out;

    int Nn = in_sizes[0] / D0;       // 100000
    int E  = in_sizes[1] / 2;        // 1600000
    int nblk_scan = (Nn + 1023) / 1024;

    const int SM12 = 66048 + 4 * RPB * D1 * 8;   // 98816 B
    cudaFuncSetAttribute(mm12_k, cudaFuncAttributeMaxDynamicSharedMemorySize, SM12);

    hist_k<<<296, 1024>>>(ei, E);                        // 0
    scan_k<<<nblk_scan, 1024>>>(Nn, E);                  // 1
    fill_k<<<296, 1024>>>(ei, E);                        // 2
    agg1_k<<<(Nn * 32 + 511) / 512, 512>>>((const float4*)x, Nn);  // 3 <- profiled
    mm12_k<<<296, 128, SM12>>>(W1, b1, W2, Nn);          // 4
    agg2_k<<<(Nn * 32 + 511) / 512, 512>>>(b2, out, Nn); // 5
}

// round 9
// speedup vs baseline: 1.2257x; 1.2257x over previous
#include <cuda_runtime.h>
#include <cstdint>

#define D0 64
#define D1 128
#define NMAX 100000
#define EMAX 1600000
#define RPB 8

// Scratch (device globals; allocation in kernel_launch is forbidden)
__device__ __align__(16) float g_t[NMAX * D0];       // 25.6 MB
__device__ __align__(16) float g_p[NMAX * D0];       // 25.6 MB
__device__ __align__(16) int   g_col[EMAX];          // 6.4 MB
__device__ int g_rowptr[NMAX + 1];
__device__ int g_cur[NMAX];
__device__ int g_cnt[NMAX];   // zero at load; re-zeroed by agg2 tail each run

// packed f32x2 FMA helpers
__device__ __forceinline__ void fma2(uint64_t& d, uint64_t a, uint64_t b) {
    asm("fma.rn.f32x2 %0, %1, %2, %0;" : "+l"(d) : "l"(a), "l"(b));
}
__device__ __forceinline__ uint64_t pack2(float v) {
    uint32_t u = __float_as_uint(v);
    uint64_t r;
    asm("mov.b64 %0, {%1, %1};" : "=l"(r) : "r"(u));
    return r;
}

// per-block int64-vs-int32 detect (odd 32-bit words all zero over 8192 = i64)
__device__ __forceinline__ bool detect64(const int* raw) {
    int nz = 0;
    for (int i = 2 * threadIdx.x + 1; i < 8192; i += 2 * blockDim.x)
        nz |= raw[i];
    return __syncthreads_or(nz) == 0;
}
__device__ __forceinline__ int eidx(const void* ei, bool is64, int i) {
    return is64 ? (int)((const long long*)ei)[i] : ((const int*)ei)[i];
}

// ---------------------------------------------------------------------------
// hist: row histogram straight off the raw edge list
// ---------------------------------------------------------------------------
__global__ __launch_bounds__(1024) void hist_k(const void* __restrict__ ei, int E) {
    bool is64 = detect64((const int*)ei);
    int stride = gridDim.x * blockDim.x;
    for (int i = blockIdx.x * blockDim.x + threadIdx.x; i < E; i += stride)
        atomicAdd(&g_cnt[eidx(ei, is64, i)], 1);
}

// ---------------------------------------------------------------------------
// scan: one-kernel exclusive prefix scan of g_cnt -> g_rowptr, g_cur
// ---------------------------------------------------------------------------
__global__ __launch_bounds__(1024) void scan_k(int Nn, int E) {
    __shared__ int sh[1024];
    __shared__ int s_off;
    int b = blockIdx.x;

    int pre = 0;
    for (int i = threadIdx.x; i < b * 1024; i += 1024) pre += g_cnt[i];
    sh[threadIdx.x] = pre;
    __syncthreads();
    #pragma unroll
    for (int off = 512; off > 0; off >>= 1) {
        if (threadIdx.x < off) sh[threadIdx.x] += sh[threadIdx.x + off];
        __syncthreads();
    }
    if (threadIdx.x == 0) s_off = sh[0];
    __syncthreads();
    int base = s_off;
    __syncthreads();

    int g = b * 1024 + threadIdx.x;
    int v = (g < Nn) ? g_cnt[g] : 0;
    sh[threadIdx.x] = v;
    __syncthreads();
    #pragma unroll
    for (int off = 1; off < 1024; off <<= 1) {
        int t = (threadIdx.x >= off) ? sh[threadIdx.x - off] : 0;
        __syncthreads();
        sh[threadIdx.x] += t;
        __syncthreads();
    }
    if (g < Nn) {
        int r = base + sh[threadIdx.x] - v;
        g_rowptr[g] = r;
        g_cur[g] = r;
    }
    if (b == 0 && threadIdx.x == 0) g_rowptr[Nn] = E;
}

// ---------------------------------------------------------------------------
// fill: CSR col array straight off the raw edge list
// ---------------------------------------------------------------------------
__global__ __launch_bounds__(1024) void fill_k(const void* __restrict__ ei, int E) {
    bool is64 = detect64((const int*)ei);
    int stride = gridDim.x * blockDim.x;
    for (int e = blockIdx.x * blockDim.x + threadIdx.x; e < E; e += stride) {
        int r = eidx(ei, is64, e);
        int c = eidx(ei, is64, e + E);
        int pos = atomicAdd(&g_cur[r], 1);
        g_col[pos] = c;
    }
}

// ---------------------------------------------------------------------------
// agg1: t[r] = (sum_{c in adj(r)} x[c]) / max(deg,1) + x[r]
// ONE ROW PER HALF-WARP: 16 lanes x float4 = full 64-float row. Two
// independent dependency chains per warp; no cross-half reduction.
// ---------------------------------------------------------------------------
__global__ __launch_bounds__(512) void agg1_k(const float4* __restrict__ x4, int Nn) {
    int w = (blockIdx.x * blockDim.x + threadIdx.x) >> 5;   // warp id
    int lane = threadIdx.x & 31;
    int hi   = lane >> 4;          // half-warp: which row of the pair
    int cl4  = lane & 15;          // float4 column within the row
    int r = 2 * w + hi;
    bool active = (r < Nn);
    int s = active ? g_rowptr[r]     : 0;
    int e = active ? g_rowptr[r + 1] : 0;

    float4 acc = make_float4(0.f, 0.f, 0.f, 0.f);
    int j = s;
    #pragma unroll 1
    for (; j + 4 <= e; j += 4) {
        int c0 = g_col[j];        // uniform within half-warp -> broadcast LDG
        int c1 = g_col[j + 1];
        int c2 = g_col[j + 2];
        int c3 = g_col[j + 3];
        float4 v0 = __ldg(&x4[c0 * 16 + cl4]);
        float4 v1 = __ldg(&x4[c1 * 16 + cl4]);
        float4 v2 = __ldg(&x4[c2 * 16 + cl4]);
        float4 v3 = __ldg(&x4[c3 * 16 + cl4]);
        acc.x += (v0.x + v1.x) + (v2.x + v3.x);
        acc.y += (v0.y + v1.y) + (v2.y + v3.y);
        acc.z += (v0.z + v1.z) + (v2.z + v3.z);
        acc.w += (v0.w + v1.w) + (v2.w + v3.w);
    }
    #pragma unroll 1
    for (; j < e; j++) {
        float4 v = __ldg(&x4[g_col[j] * 16 + cl4]);
        acc.x += v.x; acc.y += v.y; acc.z += v.z; acc.w += v.w;
    }
    if (active) {
        float inv = 1.0f / fmaxf((float)(e - s), 1.0f);
        float4 xx = __ldg(&x4[r * 16 + cl4]);
        float4 o;
        o.x = acc.x * inv + xx.x;
        o.y = acc.y * inv + xx.y;
        o.z = acc.z * inv + xx.z;
        o.w = acc.w * inv + xx.w;
        ((float4*)g_t)[r * 16 + cl4] = o;
    }
}

// ---------------------------------------------------------------------------
// mm12: fused  h = relu(t @ W1 + b1);  p = h @ W2   (exact R7 version)
// smem: sW1 32KB | sW2 32KB | sb1 512B | st 4*8*128*4B = 16KB  -> 82432 B
// ---------------------------------------------------------------------------
__global__ __launch_bounds__(128) void mm12_k(const float* __restrict__ W1,
                                              const float* __restrict__ b1,
                                              const float* __restrict__ W2,
                                              int Nn) {
    extern __shared__ char smem_[];
    float* sW1 = (float*)smem_;                 // [k][j] 64x128
    float* sW2 = (float*)(smem_ + 32768);       // [k][j] 128x64
    float* sb1 = (float*)(smem_ + 65536);
    float* st  = (float*)(smem_ + 66048);       // [warp][rr][128]

    int tid = threadIdx.x;
    for (int i = tid; i < D0 * D1; i += 128) sW1[i] = W1[i];
    for (int i = tid; i < D1 * D0; i += 128) sW2[i] = W2[i];
    if (tid < D1) sb1[tid] = b1[tid];
    __syncthreads();

    int warp = tid >> 5, lane = tid & 31;
    float* stw = st + warp * RPB * D1;
    float4 b4 = ((const float4*)sb1)[lane];
    int nwarps = gridDim.x * 4;
    int gw = blockIdx.x * 4 + warp;

    for (int base = gw * RPB; base < Nn; base += nwarps * RPB) {
        #pragma unroll
        for (int rr = 0; rr < RPB; rr++) {
            int r = base + rr;
            if (r < Nn)
                ((float2*)(stw + rr * D1))[lane] = ((const float2*)g_t)[r * 32 + lane];
        }
        __syncwarp();

        // GEMM1: lane owns h cols 4lane..4lane+3
        uint64_t accA[RPB], accB[RPB];
        #pragma unroll
        for (int rr = 0; rr < RPB; rr++) { accA[rr] = 0ull; accB[rr] = 0ull; }

        #pragma unroll 2
        for (int k4 = 0; k4 < D0; k4 += 4) {
            float4 tv[RPB];
            #pragma unroll
            for (int rr = 0; rr < RPB; rr++)
                tv[rr] = *(const float4*)(stw + rr * D1 + k4);
            #pragma unroll
            for (int kk = 0; kk < 4; kk++) {
                ulonglong2 w2 = ((const ulonglong2*)(sW1 + (k4 + kk) * D1))[lane];
                #pragma unroll
                for (int rr = 0; rr < RPB; rr++) {
                    float tk = (kk == 0) ? tv[rr].x : (kk == 1) ? tv[rr].y
                             : (kk == 2) ? tv[rr].z : tv[rr].w;
                    uint64_t tt = pack2(tk);
                    fma2(accA[rr], tt, w2.x);
                    fma2(accB[rr], tt, w2.y);
                }
            }
        }
        __syncwarp();

        // h = relu(acc+b), restage into st
        #pragma unroll
        for (int rr = 0; rr < RPB; rr++) {
            float2 aa = *(float2*)&accA[rr];
            float2 bb = *(float2*)&accB[rr];
            float4 o;
            o.x = fmaxf(aa.x + b4.x, 0.f);
            o.y = fmaxf(aa.y + b4.y, 0.f);
            o.z = fmaxf(bb.x + b4.z, 0.f);
            o.w = fmaxf(bb.y + b4.w, 0.f);
            ((float4*)(stw + rr * D1))[lane] = o;
        }
        __syncwarp();

        // GEMM2: lane owns p cols 2lane..2lane+1
        uint64_t acc[RPB];
        #pragma unroll
        for (int rr = 0; rr < RPB; rr++) acc[rr] = 0ull;

        #pragma unroll 2
        for (int k4 = 0; k4 < D1; k4 += 4) {
            float4 hv[RPB];
            #pragma unroll
            for (int rr = 0; rr < RPB; rr++)
                hv[rr] = *(const float4*)(stw + rr * D1 + k4);
            #pragma unroll
            for (int kk = 0; kk < 4; kk++) {
                uint64_t w = ((const uint64_t*)(sW2 + (k4 + kk) * D0))[lane];
                #pragma unroll
                for (int rr = 0; rr < RPB; rr++) {
                    float hk = (kk == 0) ? hv[rr].x : (kk == 1) ? hv[rr].y
                             : (kk == 2) ? hv[rr].z : hv[rr].w;
                    fma2(acc[rr], pack2(hk), w);
                }
            }
        }

        #pragma unroll
        for (int rr = 0; rr < RPB; rr++) {
            int r = base + rr;
            if (r < Nn) ((float2*)g_p)[r * 32 + lane] = *(float2*)&acc[rr];
        }
        __syncwarp();
    }
}

// ---------------------------------------------------------------------------
// agg2: out[r] = (sum_{c in adj(r)} p[c]) / max(deg,1) + p[r] + b2
// Row per half-warp. Tail: re-zero g_cnt for next graph replay.
// ---------------------------------------------------------------------------
__global__ __launch_bounds__(512) void agg2_k(const float* __restrict__ b2,
                                              float* __restrict__ out, int Nn) {
    int w = (blockIdx.x * blockDim.x + threadIdx.x) >> 5;
    int lane = threadIdx.x & 31;
    int hi   = lane >> 4;
    int cl4  = lane & 15;
    int r = 2 * w + hi;
    bool active = (r < Nn);
    const float4* p4 = (const float4*)g_p;
    int s = active ? g_rowptr[r]     : 0;
    int e = active ? g_rowptr[r + 1] : 0;

    float4 acc = make_float4(0.f, 0.f, 0.f, 0.f);
    int j = s;
    #pragma unroll 1
    for (; j + 4 <= e; j += 4) {
        int c0 = g_col[j];
        int c1 = g_col[j + 1];
        int c2 = g_col[j + 2];
        int c3 = g_col[j + 3];
        float4 v0 = p4[c0 * 16 + cl4];
        float4 v1 = p4[c1 * 16 + cl4];
        float4 v2 = p4[c2 * 16 + cl4];
        float4 v3 = p4[c3 * 16 + cl4];
        acc.x += (v0.x + v1.x) + (v2.x + v3.x);
        acc.y += (v0.y + v1.y) + (v2.y + v3.y);
        acc.z += (v0.z + v1.z) + (v2.z + v3.z);
        acc.w += (v0.w + v1.w) + (v2.w + v3.w);
    }
    #pragma unroll 1
    for (; j < e; j++) {
        float4 v = p4[g_col[j] * 16 + cl4];
        acc.x += v.x; acc.y += v.y; acc.z += v.z; acc.w += v.w;
    }
    if (active) {
        float inv = 1.0f / fmaxf((float)(e - s), 1.0f);
        float4 pp = p4[r * 16 + cl4];
        float4 bb = __ldg(&((const float4*)b2)[cl4]);
        float4 o;
        o.x = acc.x * inv + pp.x + bb.x;
        o.y = acc.y * inv + pp.y + bb.y;
        o.z = acc.z * inv + pp.z + bb.z;
        o.w = acc.w * inv + pp.w + bb.w;
        ((float4*)out)[r * 16 + cl4] = o;
        if (cl4 == 0) g_cnt[r] = 0;
    }
}

// ---------------------------------------------------------------------------
extern "C" void kernel_launch(void* const* d_in, const int* in_sizes, int n_in,
                              void* d_out, int out_size) {
    const float* x   = (const float*)d_in[0];
    const void*  ei  = d_in[1];
    const float* W1  = (const float*)d_in[2];
    const float* b1  = (const float*)d_in[3];
    const float* W2  = (const float*)d_in[4];
    const float* b2  = (const float*)d_in[5];
    float*       out = (float*)d_out;

    int Nn = in_sizes[0] / D0;       // 100000
    int E  = in_sizes[1] / 2;        // 1600000
    int nblk_scan = (Nn + 1023) / 1024;

    const int SM12 = 66048 + 4 * RPB * D1 * 4;   // 82432 B
    cudaFuncSetAttribute(mm12_k, cudaFuncAttributeMaxDynamicSharedMemorySize, SM12);

    int nwarp_agg = (Nn + 1) / 2;                       // one row per half-warp
    int nblk_agg  = (nwarp_agg * 32 + 511) / 512;

    hist_k<<<296, 1024>>>(ei, E);                        // 0
    scan_k<<<nblk_scan, 1024>>>(Nn, E);                  // 1
    fill_k<<<296, 1024>>>(ei, E);                        // 2
    agg1_k<<<nblk_agg, 512>>>((const float4*)x, Nn);     // 3 <- profiled
    mm12_k<<<296, 128, SM12>>>(W1, b1, W2, Nn);          // 4
    agg2_k<<<nblk_agg, 512>>>(b2, out, Nn);              // 5
}

// round 10
// speedup vs baseline: 1.5597x; 1.2725x over previous
#include <cuda_runtime.h>
#include <cstdint>

#define D0 64
#define D1 128
#define NMAX 100000
#define EMAX 1600000

// Scratch (device globals; allocation in kernel_launch is forbidden)
__device__ __align__(16) float g_t[NMAX * D0];       // 25.6 MB
__device__ __align__(16) float g_p[NMAX * D0];       // 25.6 MB
__device__ __align__(16) int   g_col[EMAX];          // 6.4 MB
__device__ int g_rowptr[NMAX + 1];
__device__ int g_cur[NMAX];
__device__ int g_cnt[NMAX];   // zero at load; re-zeroed by agg2 tail each run

// per-block int64-vs-int32 detect (odd 32-bit words all zero over 8192 = i64)
__device__ __forceinline__ bool detect64(const int* raw) {
    int nz = 0;
    for (int i = 2 * threadIdx.x + 1; i < 8192; i += 2 * blockDim.x)
        nz |= raw[i];
    return __syncthreads_or(nz) == 0;
}
__device__ __forceinline__ int eidx(const void* ei, bool is64, int i) {
    return is64 ? (int)((const long long*)ei)[i] : ((const int*)ei)[i];
}

__device__ __forceinline__ float totf32(float x) {
    uint32_t u;
    asm("cvt.rna.tf32.f32 %0, %1;" : "=r"(u) : "f"(x));
    return __uint_as_float(u);
}

__device__ __forceinline__ void mma_tf32(float* d,
                                         uint32_t a0, uint32_t a1,
                                         uint32_t a2, uint32_t a3,
                                         uint32_t b0, uint32_t b1) {
    asm volatile(
        "mma.sync.aligned.m16n8k8.row.col.f32.tf32.tf32.f32 "
        "{%0,%1,%2,%3}, {%4,%5,%6,%7}, {%8,%9}, {%0,%1,%2,%3};"
        : "+f"(d[0]), "+f"(d[1]), "+f"(d[2]), "+f"(d[3])
        : "r"(a0), "r"(a1), "r"(a2), "r"(a3), "r"(b0), "r"(b1));
}

// ---------------------------------------------------------------------------
// hist: row histogram straight off the raw edge list
// ---------------------------------------------------------------------------
__global__ __launch_bounds__(1024) void hist_k(const void* __restrict__ ei, int E) {
    bool is64 = detect64((const int*)ei);
    int stride = gridDim.x * blockDim.x;
    for (int i = blockIdx.x * blockDim.x + threadIdx.x; i < E; i += stride)
        atomicAdd(&g_cnt[eidx(ei, is64, i)], 1);
}

// ---------------------------------------------------------------------------
// scan: one-kernel exclusive prefix scan of g_cnt -> g_rowptr, g_cur
// ---------------------------------------------------------------------------
__global__ __launch_bounds__(1024) void scan_k(int Nn, int E) {
    __shared__ int sh[1024];
    __shared__ int s_off;
    int b = blockIdx.x;

    int pre = 0;
    for (int i = threadIdx.x; i < b * 1024; i += 1024) pre += g_cnt[i];
    sh[threadIdx.x] = pre;
    __syncthreads();
    #pragma unroll
    for (int off = 512; off > 0; off >>= 1) {
        if (threadIdx.x < off) sh[threadIdx.x] += sh[threadIdx.x + off];
        __syncthreads();
    }
    if (threadIdx.x == 0) s_off = sh[0];
    __syncthreads();
    int base = s_off;
    __syncthreads();

    int g = b * 1024 + threadIdx.x;
    int v = (g < Nn) ? g_cnt[g] : 0;
    sh[threadIdx.x] = v;
    __syncthreads();
    #pragma unroll
    for (int off = 1; off < 1024; off <<= 1) {
        int t = (threadIdx.x >= off) ? sh[threadIdx.x - off] : 0;
        __syncthreads();
        sh[threadIdx.x] += t;
        __syncthreads();
    }
    if (g < Nn) {
        int r = base + sh[threadIdx.x] - v;
        g_rowptr[g] = r;
        g_cur[g] = r;
    }
    if (b == 0 && threadIdx.x == 0) g_rowptr[Nn] = E;
}

// ---------------------------------------------------------------------------
// fill: CSR col array straight off the raw edge list
// ---------------------------------------------------------------------------
__global__ __launch_bounds__(1024) void fill_k(const void* __restrict__ ei, int E) {
    bool is64 = detect64((const int*)ei);
    int stride = gridDim.x * blockDim.x;
    for (int e = blockIdx.x * blockDim.x + threadIdx.x; e < E; e += stride) {
        int r = eidx(ei, is64, e);
        int c = eidx(ei, is64, e + E);
        int pos = atomicAdd(&g_cur[r], 1);
        g_col[pos] = c;
    }
}

// ---------------------------------------------------------------------------
// agg1: t[r] = (sum_{c in adj(r)} x[c]) / max(deg,1) + x[r]
// One row per half-warp (exact R9 version).
// ---------------------------------------------------------------------------
__global__ __launch_bounds__(512) void agg1_k(const float4* __restrict__ x4, int Nn) {
    int w = (blockIdx.x * blockDim.x + threadIdx.x) >> 5;
    int lane = threadIdx.x & 31;
    int hi   = lane >> 4;
    int cl4  = lane & 15;
    int r = 2 * w + hi;
    bool active = (r < Nn);
    int s = active ? g_rowptr[r]     : 0;
    int e = active ? g_rowptr[r + 1] : 0;

    float4 acc = make_float4(0.f, 0.f, 0.f, 0.f);
    int j = s;
    #pragma unroll 1
    for (; j + 4 <= e; j += 4) {
        int c0 = g_col[j];
        int c1 = g_col[j + 1];
        int c2 = g_col[j + 2];
        int c3 = g_col[j + 3];
        float4 v0 = __ldg(&x4[c0 * 16 + cl4]);
        float4 v1 = __ldg(&x4[c1 * 16 + cl4]);
        float4 v2 = __ldg(&x4[c2 * 16 + cl4]);
        float4 v3 = __ldg(&x4[c3 * 16 + cl4]);
        acc.x += (v0.x + v1.x) + (v2.x + v3.x);
        acc.y += (v0.y + v1.y) + (v2.y + v3.y);
        acc.z += (v0.z + v1.z) + (v2.z + v3.z);
        acc.w += (v0.w + v1.w) + (v2.w + v3.w);
    }
    #pragma unroll 1
    for (; j < e; j++) {
        float4 v = __ldg(&x4[g_col[j] * 16 + cl4]);
        acc.x += v.x; acc.y += v.y; acc.z += v.z; acc.w += v.w;
    }
    if (active) {
        float inv = 1.0f / fmaxf((float)(e - s), 1.0f);
        float4 xx = __ldg(&x4[r * 16 + cl4]);
        float4 o;
        o.x = acc.x * inv + xx.x;
        o.y = acc.y * inv + xx.y;
        o.z = acc.z * inv + xx.z;
        o.w = acc.w * inv + xx.w;
        ((float4*)g_t)[r * 16 + cl4] = o;
    }
}

// ---------------------------------------------------------------------------
// mm12_tc: fused tf32 tensor-core GEMMs.
//   h = relu(t @ W1 + b1);  p = h @ W2
// 256 threads (8 warps), 128 rows/block-iter, warp owns 16 rows end-to-end.
// smem (floats, padded strides for conflict-free fragment LDS):
//   sW1 [64 ][136]  @ 0        (34816 B)
//   sW2 [128][72 ]  @ 34816    (36864 B)
//   sb1 [128]       @ 71680    (512 B)
//   st  [128][132]  @ 72192    (67584 B)   t cols 0..63, then h cols 0..127
// total 139776 B -> 1 block/SM.
// ---------------------------------------------------------------------------
__global__ __launch_bounds__(256) void mm12_tc(const float* __restrict__ W1,
                                               const float* __restrict__ b1,
                                               const float* __restrict__ W2,
                                               int Nn) {
    extern __shared__ char smem_[];
    float* sW1 = (float*)smem_;
    float* sW2 = (float*)(smem_ + 34816);
    float* sb1 = (float*)(smem_ + 71680);
    float* st  = (float*)(smem_ + 72192);

    int tid = threadIdx.x;
    for (int i = tid; i < D0 * D1; i += 256) {
        int k = i >> 7, n = i & 127;
        sW1[k * 136 + n] = totf32(W1[i]);
    }
    for (int i = tid; i < D1 * D0; i += 256) {
        int k = i >> 6, n = i & 63;
        sW2[k * 72 + n] = totf32(W2[i]);
    }
    if (tid < D1) sb1[tid] = b1[tid];
    __syncthreads();

    int warp = tid >> 5, lane = tid & 31;
    int g   = lane >> 2;      // group id 0..7
    int tig = lane & 3;       // thread in group
    int m0  = warp * 16;

    for (int base = blockIdx.x * 128; base < Nn; base += gridDim.x * 128) {
        // --- stage t (tf32-rounded) ---
        for (int idx = tid; idx < 128 * 32; idx += 256) {
            int r = idx >> 5, c2 = idx & 31;
            float2 v = (base + r < Nn)
                     ? ((const float2*)g_t)[(base + r) * 32 + c2]
                     : make_float2(0.f, 0.f);
            st[r * 132 + 2 * c2]     = totf32(v.x);
            st[r * 132 + 2 * c2 + 1] = totf32(v.y);
        }
        __syncthreads();

        // --- GEMM1: d1[16 n-tiles] over k=64 ---
        float d1[16][4];
        #pragma unroll
        for (int nt = 0; nt < 16; nt++)
            d1[nt][0] = d1[nt][1] = d1[nt][2] = d1[nt][3] = 0.f;

        #pragma unroll 2
        for (int ks = 0; ks < 8; ks++) {
            int k0 = ks * 8;
            const float* A = st + m0 * 132 + k0;
            uint32_t a0 = __float_as_uint(A[g * 132 + tig]);
            uint32_t a1 = __float_as_uint(A[(g + 8) * 132 + tig]);
            uint32_t a2 = __float_as_uint(A[g * 132 + tig + 4]);
            uint32_t a3 = __float_as_uint(A[(g + 8) * 132 + tig + 4]);
            const float* B0 = sW1 + (k0 + tig) * 136 + g;
            const float* B1 = sW1 + (k0 + tig + 4) * 136 + g;
            #pragma unroll
            for (int nt = 0; nt < 16; nt++) {
                uint32_t b0 = __float_as_uint(B0[nt * 8]);
                uint32_t b1v = __float_as_uint(B1[nt * 8]);
                mma_tf32(d1[nt], a0, a1, a2, a3, b0, b1v);
            }
        }
        __syncwarp();

        // --- h = relu(d1 + b1) -> restage into st (warp-private rows) ---
        #pragma unroll
        for (int nt = 0; nt < 16; nt++) {
            int n0 = nt * 8;
            int c0 = n0 + 2 * tig, c1 = c0 + 1;
            float bb0 = sb1[c0], bb1 = sb1[c1];
            st[(m0 + g) * 132 + c0]     = totf32(fmaxf(d1[nt][0] + bb0, 0.f));
            st[(m0 + g) * 132 + c1]     = totf32(fmaxf(d1[nt][1] + bb1, 0.f));
            st[(m0 + g + 8) * 132 + c0] = totf32(fmaxf(d1[nt][2] + bb0, 0.f));
            st[(m0 + g + 8) * 132 + c1] = totf32(fmaxf(d1[nt][3] + bb1, 0.f));
        }
        __syncwarp();

        // --- GEMM2: d2[8 n-tiles] over k=128 ---
        float d2[8][4];
        #pragma unroll
        for (int nt = 0; nt < 8; nt++)
            d2[nt][0] = d2[nt][1] = d2[nt][2] = d2[nt][3] = 0.f;

        #pragma unroll 2
        for (int ks = 0; ks < 16; ks++) {
            int k0 = ks * 8;
            const float* A = st + m0 * 132 + k0;
            uint32_t a0 = __float_as_uint(A[g * 132 + tig]);
            uint32_t a1 = __float_as_uint(A[(g + 8) * 132 + tig]);
            uint32_t a2 = __float_as_uint(A[g * 132 + tig + 4]);
            uint32_t a3 = __float_as_uint(A[(g + 8) * 132 + tig + 4]);
            const float* B0 = sW2 + (k0 + tig) * 72 + g;
            const float* B1 = sW2 + (k0 + tig + 4) * 72 + g;
            #pragma unroll
            for (int nt = 0; nt < 8; nt++) {
                uint32_t b0 = __float_as_uint(B0[nt * 8]);
                uint32_t b1v = __float_as_uint(B1[nt * 8]);
                mma_tf32(d2[nt], a0, a1, a2, a3, b0, b1v);
            }
        }

        // --- store p ---
        int r1 = base + m0 + g;
        int r2 = r1 + 8;
        #pragma unroll
        for (int nt = 0; nt < 8; nt++) {
            int f2i = nt * 4 + tig;   // float2 index of cols (8nt+2tig, +1)
            if (r1 < Nn)
                ((float2*)g_p)[r1 * 32 + f2i] = make_float2(d2[nt][0], d2[nt][1]);
            if (r2 < Nn)
                ((float2*)g_p)[r2 * 32 + f2i] = make_float2(d2[nt][2], d2[nt][3]);
        }
        __syncthreads();   // st reused next iteration
    }
}

// ---------------------------------------------------------------------------
// agg2: out[r] = (sum_{c in adj(r)} p[c]) / max(deg,1) + p[r] + b2
// Row per half-warp (exact R9). Tail: re-zero g_cnt for next graph replay.
// ---------------------------------------------------------------------------
__global__ __launch_bounds__(512) void agg2_k(const float* __restrict__ b2,
                                              float* __restrict__ out, int Nn) {
    int w = (blockIdx.x * blockDim.x + threadIdx.x) >> 5;
    int lane = threadIdx.x & 31;
    int hi   = lane >> 4;
    int cl4  = lane & 15;
    int r = 2 * w + hi;
    bool active = (r < Nn);
    const float4* p4 = (const float4*)g_p;
    int s = active ? g_rowptr[r]     : 0;
    int e = active ? g_rowptr[r + 1] : 0;

    float4 acc = make_float4(0.f, 0.f, 0.f, 0.f);
    int j = s;
    #pragma unroll 1
    for (; j + 4 <= e; j += 4) {
        int c0 = g_col[j];
        int c1 = g_col[j + 1];
        int c2 = g_col[j + 2];
        int c3 = g_col[j + 3];
        float4 v0 = p4[c0 * 16 + cl4];
        float4 v1 = p4[c1 * 16 + cl4];
        float4 v2 = p4[c2 * 16 + cl4];
        float4 v3 = p4[c3 * 16 + cl4];
        acc.x += (v0.x + v1.x) + (v2.x + v3.x);
        acc.y += (v0.y + v1.y) + (v2.y + v3.y);
        acc.z += (v0.z + v1.z) + (v2.z + v3.z);
        acc.w += (v0.w + v1.w) + (v2.w + v3.w);
    }
    #pragma unroll 1
    for (; j < e; j++) {
        float4 v = p4[g_col[j] * 16 + cl4];
        acc.x += v.x; acc.y += v.y; acc.z += v.z; acc.w += v.w;
    }
    if (active) {
        float inv = 1.0f / fmaxf((float)(e - s), 1.0f);
        float4 pp = p4[r * 16 + cl4];
        float4 bb = __ldg(&((const float4*)b2)[cl4]);
        float4 o;
        o.x = acc.x * inv + pp.x + bb.x;
        o.y = acc.y * inv + pp.y + bb.y;
        o.z = acc.z * inv + pp.z + bb.z;
        o.w = acc.w * inv + pp.w + bb.w;
        ((float4*)out)[r * 16 + cl4] = o;
        if (cl4 == 0) g_cnt[r] = 0;
    }
}

// ---------------------------------------------------------------------------
extern "C" void kernel_launch(void* const* d_in, const int* in_sizes, int n_in,
                              void* d_out, int out_size) {
    const float* x   = (const float*)d_in[0];
    const void*  ei  = d_in[1];
    const float* W1  = (const float*)d_in[2];
    const float* b1  = (const float*)d_in[3];
    const float* W2  = (const float*)d_in[4];
    const float* b2  = (const float*)d_in[5];
    float*       out = (float*)d_out;

    int Nn = in_sizes[0] / D0;       // 100000
    int E  = in_sizes[1] / 2;        // 1600000
    int nblk_scan = (Nn + 1023) / 1024;

    const int SM12 = 139776;
    cudaFuncSetAttribute(mm12_tc, cudaFuncAttributeMaxDynamicSharedMemorySize, SM12);

    int nwarp_agg = (Nn + 1) / 2;
    int nblk_agg  = (nwarp_agg * 32 + 511) / 512;

    hist_k<<<296, 1024>>>(ei, E);                        // 0
    scan_k<<<nblk_scan, 1024>>>(Nn, E);                  // 1
    fill_k<<<296, 1024>>>(ei, E);                        // 2
    agg1_k<<<nblk_agg, 512>>>((const float4*)x, Nn);     // 3 <- profiled
    mm12_tc<<<148, 256, SM12>>>(W1, b1, W2, Nn);         // 4
    agg2_k<<<nblk_agg, 512>>>(b2, out, Nn);              // 5
}